// round 7
// baseline (speedup 1.0000x reference)
#include <cuda_runtime.h>
#include <cuda_bf16.h>
#include <math.h>

#define S_LEN 4096
#define NH 16
#define DK 128
#define DV 128
#define CC 64
#define NCHUNK (S_LEN / CC)
#define SPLIT 4
#define DVS (DV / SPLIT)
#define NT 256

#define KHS 136
#define AS2 72
#define VS  36
#define VTS 72

struct __align__(16) SmemT {
    float v[CC * VS];
    float qraw[CC * 128], kraw[CC * 128], vraw[CC * 32];
    float gst[CC], bst[CC];
    float egc[CC], iegc[CC], kdec[CC], kw[CC], negbe[CC];
    __nv_bfloat16 khi[CC * KHS], klo[CC * KHS];
    __nv_bfloat16 qhi[CC * KHS], qlo[CC * KHS];
    __nv_bfloat16 shi[32 * KHS], slo[32 * KHS];
    __nv_bfloat16 abhi[CC * AS2], ablo[CC * AS2];  // A strict-lower; diag -> Ti
    __nv_bfloat16 athi[CC * AS2], atlo[CC * AS2];  // attn = accQ*e^{-gj}, i>=j
    __nv_bfloat16 vthi[32 * VTS], vtlo[32 * VTS];  // v_new^T
    __nv_bfloat16 rhi[32 * VTS], rlo[32 * VTS];    // rhs blk; later vd=(v_new*kdec)^T
};

__device__ __forceinline__ void bsplit(float x, __nv_bfloat16& hi, __nv_bfloat16& lo) {
    hi = __float2bfloat16(x);
    lo = __float2bfloat16(x - __bfloat162float(hi));
}
__device__ __forceinline__ void bsplit2(float x0, float x1, unsigned& h, unsigned& l) {
    __nv_bfloat16 h0 = __float2bfloat16(x0), h1 = __float2bfloat16(x1);
    __nv_bfloat16 g0 = __float2bfloat16(x0 - __bfloat162float(h0));
    __nv_bfloat16 g1 = __float2bfloat16(x1 - __bfloat162float(h1));
    h = (unsigned)*(unsigned short*)&h0 | ((unsigned)*(unsigned short*)&h1 << 16);
    l = (unsigned)*(unsigned short*)&g0 | ((unsigned)*(unsigned short*)&g1 << 16);
}
__device__ __forceinline__ unsigned sm_addr(const void* p) {
    return (unsigned)__cvta_generic_to_shared(p);
}
__device__ __forceinline__ void ldsm4(unsigned* r, unsigned a) {
    asm volatile("ldmatrix.sync.aligned.m8n8.x4.shared.b16 {%0,%1,%2,%3}, [%4];"
                 : "=r"(r[0]), "=r"(r[1]), "=r"(r[2]), "=r"(r[3]) : "r"(a));
}
__device__ __forceinline__ void ldsm2(unsigned* r, unsigned a) {
    asm volatile("ldmatrix.sync.aligned.m8n8.x2.shared.b16 {%0,%1}, [%2];"
                 : "=r"(r[0]), "=r"(r[1]) : "r"(a));
}
__device__ __forceinline__ void mma16816(float* d, unsigned a0, unsigned a1,
                                         unsigned a2, unsigned a3,
                                         unsigned b0, unsigned b1) {
    asm volatile(
        "mma.sync.aligned.m16n8k16.row.col.f32.bf16.bf16.f32 "
        "{%0,%1,%2,%3}, {%4,%5,%6,%7}, {%8,%9}, {%0,%1,%2,%3};\n"
        : "+f"(d[0]), "+f"(d[1]), "+f"(d[2]), "+f"(d[3])
        : "r"(a0), "r"(a1), "r"(a2), "r"(a3), "r"(b0), "r"(b1));
}
__device__ __forceinline__ void mma_p3(float* d, const unsigned* ah, const unsigned* al,
                                       unsigned bh0, unsigned bh1,
                                       unsigned bl0, unsigned bl1) {
    mma16816(d, ah[0], ah[1], ah[2], ah[3], bh0, bh1);
    mma16816(d, ah[0], ah[1], ah[2], ah[3], bl0, bl1);
    mma16816(d, al[0], al[1], al[2], al[3], bh0, bh1);
}
__device__ __forceinline__ void ldBtrans(const __nv_bfloat16* p, int stride, int n,
                                         int k0, int tig, unsigned* bb) {
    const unsigned short* s = reinterpret_cast<const unsigned short*>(p);
    int r = k0 + 2 * tig;
    unsigned l0 = s[r * stride + n], h0 = s[(r + 1) * stride + n];
    unsigned l1 = s[(r + 8) * stride + n], h1 = s[(r + 9) * stride + n];
    bb[0] = l0 | (h0 << 16);
    bb[1] = l1 | (h1 << 16);
}
__device__ __forceinline__ void cpa16(void* dst, const void* src) {
    unsigned d = (unsigned)__cvta_generic_to_shared(dst);
    asm volatile("cp.async.cg.shared.global [%0], [%1], 16;\n" :: "r"(d), "l"(src));
}
__device__ __forceinline__ void cpa4(void* dst, const void* src) {
    unsigned d = (unsigned)__cvta_generic_to_shared(dst);
    asm volatile("cp.async.ca.shared.global [%0], [%1], 4;\n" :: "r"(d), "l"(src));
}
__device__ __forceinline__ void prefetch_chunk(SmemT& sm, int m, int b, int h,
                                               int split, int tid,
                                               const float* gq, const float* gk,
                                               const float* gv, const float* gg,
                                               const float* gb) {
    for (int i = tid; i < CC * 32; i += NT) {
        int r = i >> 5, cq = i & 31;
        size_t rowb = (((size_t)b * S_LEN + m * CC + r) * NH + h) * (size_t)DK;
        cpa16(&sm.qraw[r * 128 + cq * 4], gq + rowb + cq * 4);
        cpa16(&sm.kraw[r * 128 + cq * 4], gk + rowb + cq * 4);
    }
    for (int i = tid; i < CC * 8; i += NT) {
        int r = i >> 3, cq = i & 7;
        size_t rowb = (((size_t)b * S_LEN + m * CC + r) * NH + h) * (size_t)DV;
        cpa16(&sm.vraw[r * 32 + cq * 4], gv + rowb + split * DVS + cq * 4);
    }
    if (tid < CC) {
        size_t gi = ((size_t)b * S_LEN + m * CC + tid) * NH + h;
        cpa4(&sm.gst[tid], gg + gi);
        cpa4(&sm.bst[tid], gb + gi);
    }
    asm volatile("cp.async.commit_group;\n");
}

__global__ __launch_bounds__(NT, 1)
void gdn_kernel(const float* __restrict__ gq, const float* __restrict__ gk,
                const float* __restrict__ gv, const float* __restrict__ gg,
                const float* __restrict__ gb, float* __restrict__ gout) {
    extern __shared__ char smem_raw[];
    SmemT& sm = *reinterpret_cast<SmemT*>(smem_raw);
    const int tid = threadIdx.x;
    const int bh = blockIdx.x / SPLIT;
    const int split = blockIdx.x % SPLIT;
    const int b = bh / NH, h = bh % NH;
    const int warp = tid >> 5, lane = tid & 31;
    const int gq_ = lane >> 2, tig = lane & 3;
    const int lr = lane & 15, lc8 = (lane >> 4) << 3;       // ldsm x4
    const int lr2 = lane & 7, lc2 = ((lane >> 3) & 1) << 3; // ldsm x2

    const __nv_bfloat16 bz = __float2bfloat16(0.f);
    for (int i = tid; i < 32 * KHS; i += NT) { sm.shi[i] = bz; sm.slo[i] = bz; }

    prefetch_chunk(sm, 0, b, h, split, tid, gq, gk, gv, gg, gb);
    const float QSCALE = 0.08838834764831845f;

    for (int n = 0; n < NCHUNK; ++n) {
        const int s0 = n * CC;
        asm volatile("cp.async.wait_group 0;\n");
        __syncthreads();

        // phase A
        if (warp == 0) {
            float a0 = sm.gst[lane], a1 = sm.gst[lane + 32];
#pragma unroll
            for (int off = 1; off < 32; off <<= 1) {
                float t = __shfl_up_sync(0xffffffffu, a0, off);
                if (lane >= off) a0 += t;
            }
            float tot0 = __shfl_sync(0xffffffffu, a0, 31);
#pragma unroll
            for (int off = 1; off < 32; off <<= 1) {
                float t = __shfl_up_sync(0xffffffffu, a1, off);
                if (lane >= off) a1 += t;
            }
            a1 += tot0;
            float glast = __shfl_sync(0xffffffffu, a1, 31);
            float e0 = expf(a0), e1 = expf(a1);
            sm.egc[lane] = e0;                sm.egc[lane + 32] = e1;
            sm.iegc[lane] = expf(-a0);        sm.iegc[lane + 32] = expf(-a1);
            sm.kdec[lane] = expf(glast - a0); sm.kdec[lane + 32] = expf(glast - a1);
            float b0 = sm.bst[lane], b1 = sm.bst[lane + 32];
            sm.kw[lane] = b0 * e0;            sm.kw[lane + 32] = b1 * e1;
            sm.negbe[lane] = -b0 * e0;        sm.negbe[lane + 32] = -b1 * e1;
        } else {
            for (int i = tid - 32; i < CC * 8; i += NT - 32) {
                int r = i >> 3, cq = i & 7;
                float4 t = *reinterpret_cast<const float4*>(&sm.vraw[r * 32 + cq * 4]);
                float bt = sm.bst[r];
                t.x *= bt; t.y *= bt; t.z *= bt; t.w *= bt;
                *reinterpret_cast<float4*>(&sm.v[r * VS + cq * 4]) = t;
            }
        }
        __syncthreads();

        // phase B: norm+split, 2 rows/iter
#pragma unroll
        for (int it = 0; it < 4; ++it) {
            int r0 = warp + it * 16, r1 = r0 + 8;
            float4 qv0 = *reinterpret_cast<const float4*>(&sm.qraw[r0 * 128 + lane * 4]);
            float4 kv0 = *reinterpret_cast<const float4*>(&sm.kraw[r0 * 128 + lane * 4]);
            float4 qv1 = *reinterpret_cast<const float4*>(&sm.qraw[r1 * 128 + lane * 4]);
            float4 kv1 = *reinterpret_cast<const float4*>(&sm.kraw[r1 * 128 + lane * 4]);
            float sq0 = qv0.x*qv0.x + qv0.y*qv0.y + qv0.z*qv0.z + qv0.w*qv0.w;
            float sk0 = kv0.x*kv0.x + kv0.y*kv0.y + kv0.z*kv0.z + kv0.w*kv0.w;
            float sq1 = qv1.x*qv1.x + qv1.y*qv1.y + qv1.z*qv1.z + qv1.w*qv1.w;
            float sk1 = kv1.x*kv1.x + kv1.y*kv1.y + kv1.z*kv1.z + kv1.w*kv1.w;
#pragma unroll
            for (int o = 16; o > 0; o >>= 1) {
                sq0 += __shfl_xor_sync(0xffffffffu, sq0, o);
                sk0 += __shfl_xor_sync(0xffffffffu, sk0, o);
                sq1 += __shfl_xor_sync(0xffffffffu, sq1, o);
                sk1 += __shfl_xor_sync(0xffffffffu, sk1, o);
            }
            float rq0 = rsqrtf(sq0 + 1e-6f) * QSCALE * sm.egc[r0];
            float rk0 = rsqrtf(sk0 + 1e-6f);
            float rq1 = rsqrtf(sq1 + 1e-6f) * QSCALE * sm.egc[r1];
            float rk1 = rsqrtf(sk1 + 1e-6f);
            int c4 = lane * 4;
            unsigned hh, ll;
            bsplit2(kv0.x*rk0, kv0.y*rk0, hh, ll);
            *(unsigned*)&sm.khi[r0*KHS + c4] = hh; *(unsigned*)&sm.klo[r0*KHS + c4] = ll;
            bsplit2(kv0.z*rk0, kv0.w*rk0, hh, ll);
            *(unsigned*)&sm.khi[r0*KHS + c4+2] = hh; *(unsigned*)&sm.klo[r0*KHS + c4+2] = ll;
            bsplit2(qv0.x*rq0, qv0.y*rq0, hh, ll);
            *(unsigned*)&sm.qhi[r0*KHS + c4] = hh; *(unsigned*)&sm.qlo[r0*KHS + c4] = ll;
            bsplit2(qv0.z*rq0, qv0.w*rq0, hh, ll);
            *(unsigned*)&sm.qhi[r0*KHS + c4+2] = hh; *(unsigned*)&sm.qlo[r0*KHS + c4+2] = ll;
            bsplit2(kv1.x*rk1, kv1.y*rk1, hh, ll);
            *(unsigned*)&sm.khi[r1*KHS + c4] = hh; *(unsigned*)&sm.klo[r1*KHS + c4] = ll;
            bsplit2(kv1.z*rk1, kv1.w*rk1, hh, ll);
            *(unsigned*)&sm.khi[r1*KHS + c4+2] = hh; *(unsigned*)&sm.klo[r1*KHS + c4+2] = ll;
            bsplit2(qv1.x*rq1, qv1.y*rq1, hh, ll);
            *(unsigned*)&sm.qhi[r1*KHS + c4] = hh; *(unsigned*)&sm.qlo[r1*KHS + c4] = ll;
            bsplit2(qv1.z*rq1, qv1.w*rq1, hh, ll);
            *(unsigned*)&sm.qhi[r1*KHS + c4+2] = hh; *(unsigned*)&sm.qlo[r1*KHS + c4+2] = ll;
        }
        __syncthreads();

        if (n + 1 < NCHUNK)
            prefetch_chunk(sm, n + 1, b, h, split, tid, gq, gk, gv, gg, gb);

        // P1: G=K@K^T, QK=Qg@K^T
        {
            const int m0 = (warp >> 1) * 16, n0 = (warp & 1) * 32;
            float accG[4][4] = {}, accQ[4][4] = {};
            if (m0 + 15 >= n0) {
                unsigned aKh = sm_addr(&sm.khi[(m0+lr)*KHS + lc8]);
                unsigned aKl = sm_addr(&sm.klo[(m0+lr)*KHS + lc8]);
                unsigned aQh = sm_addr(&sm.qhi[(m0+lr)*KHS + lc8]);
                unsigned aQl = sm_addr(&sm.qlo[(m0+lr)*KHS + lc8]);
                unsigned b0ha = sm_addr(&sm.khi[(n0+lr)*KHS + lc8]);
                unsigned b0la = sm_addr(&sm.klo[(n0+lr)*KHS + lc8]);
                unsigned b1ha = sm_addr(&sm.khi[(n0+16+lr)*KHS + lc8]);
                unsigned b1la = sm_addr(&sm.klo[(n0+16+lr)*KHS + lc8]);
                const bool d1 = (m0+15 >= n0+8), d2 = (m0+15 >= n0+16),
                           d3 = (m0+15 >= n0+24);
                for (int k0 = 0; k0 < DK; k0 += 16) {
                    unsigned kh[4], kl[4], qh[4], ql[4], b0h[4], b0l[4];
                    ldsm4(kh, aKh + k0*2); ldsm4(kl, aKl + k0*2);
                    ldsm4(qh, aQh + k0*2); ldsm4(ql, aQl + k0*2);
                    ldsm4(b0h, b0ha + k0*2); ldsm4(b0l, b0la + k0*2);
                    mma_p3(accG[0], kh, kl, b0h[0], b0h[2], b0l[0], b0l[2]);
                    mma_p3(accQ[0], qh, ql, b0h[0], b0h[2], b0l[0], b0l[2]);
                    if (d1) {
                        mma_p3(accG[1], kh, kl, b0h[1], b0h[3], b0l[1], b0l[3]);
                        mma_p3(accQ[1], qh, ql, b0h[1], b0h[3], b0l[1], b0l[3]);
                    }
                    if (d2) {
                        unsigned b1h[4], b1l[4];
                        ldsm4(b1h, b1ha + k0*2); ldsm4(b1l, b1la + k0*2);
                        mma_p3(accG[2], kh, kl, b1h[0], b1h[2], b1l[0], b1l[2]);
                        mma_p3(accQ[2], qh, ql, b1h[0], b1h[2], b1l[0], b1l[2]);
                        if (d3) {
                            mma_p3(accG[3], kh, kl, b1h[1], b1h[3], b1l[1], b1l[3]);
                            mma_p3(accQ[3], qh, ql, b1h[1], b1h[3], b1l[1], b1l[3]);
                        }
                    }
                }
            }
#pragma unroll
            for (int nt = 0; nt < 4; ++nt) {
                int j0 = n0 + nt * 8 + 2 * tig;
                float ie0 = sm.iegc[j0], ie1 = sm.iegc[j0 + 1];
#pragma unroll
                for (int rh = 0; rh < 2; ++rh) {
                    int i = m0 + gq_ + rh * 8;
                    float nb = sm.negbe[i];
                    float av0 = (i > j0)      ? nb * ie0 * accG[nt][rh*2]   : 0.f;
                    float av1 = (i > j0 + 1)  ? nb * ie1 * accG[nt][rh*2+1] : 0.f;
                    float at0 = (i >= j0)     ? accQ[nt][rh*2]   * ie0 : 0.f;
                    float at1 = (i >= j0 + 1) ? accQ[nt][rh*2+1] * ie1 : 0.f;
                    unsigned hh, ll;
                    bsplit2(av0, av1, hh, ll);
                    *(unsigned*)&sm.abhi[i*AS2 + j0] = hh;
                    *(unsigned*)&sm.ablo[i*AS2 + j0] = ll;
                    bsplit2(at0, at1, hh, ll);
                    *(unsigned*)&sm.athi[i*AS2 + j0] = hh;
                    *(unsigned*)&sm.atlo[i*AS2 + j0] = ll;
                }
            }
        }

        // P2: rhs -= kw * (K @ State)
        {
            const int m0 = (warp & 1) * 16, n0 = (warp >> 1) * 16;
            float acc[2][4] = {};
            unsigned aSh = sm_addr(&sm.shi[(m0+lr)*KHS + lc8]);
            unsigned aSl = sm_addr(&sm.slo[(m0+lr)*KHS + lc8]);
            unsigned bKh = sm_addr(&sm.khi[(n0+lr)*KHS + lc8]);
            unsigned bKl = sm_addr(&sm.klo[(n0+lr)*KHS + lc8]);
            for (int k0 = 0; k0 < DK; k0 += 16) {
                unsigned ah[4], al[4], bh4[4], bl4[4];
                ldsm4(ah, aSh + k0*2); ldsm4(al, aSl + k0*2);
                ldsm4(bh4, bKh + k0*2); ldsm4(bl4, bKl + k0*2);
                mma_p3(acc[0], ah, al, bh4[0], bh4[2], bl4[0], bl4[2]);
                mma_p3(acc[1], ah, al, bh4[1], bh4[3], bl4[1], bl4[3]);
            }
#pragma unroll
            for (int nt = 0; nt < 2; ++nt)
#pragma unroll
                for (int e = 0; e < 4; ++e) {
                    int i = m0 + gq_ + ((e >> 1) << 3);
                    int j = n0 + nt * 8 + 2 * tig + (e & 1);
                    sm.v[j * VS + i] -= sm.kw[j] * acc[nt][e];
                }
        }
        __syncthreads();

        // S1: warps 0-3 invert diag blocks -> Ti (bf16, into abhi/ablo diag);
        //     warps 4-7 split rhs block0 into rhi/rlo
        if (warp < 4) {
            const int r0 = warp * 16;
            if (lane < 16) {
                float x[16];
#pragma unroll
                for (int r = 0; r < 16; ++r) {
                    float acc = (r == lane) ? 1.f : 0.f;
#pragma unroll
                    for (int j = 0; j < 16; ++j)
                        if (j < r) {
                            float a = __bfloat162float(sm.abhi[(r0+r)*AS2 + r0+j]) +
                                      __bfloat162float(sm.ablo[(r0+r)*AS2 + r0+j]);
                            acc += a * x[j];
                        }
                    x[r] = acc;
                }
                __syncwarp(0x0000ffffu);
#pragma unroll
                for (int r = 0; r < 16; ++r) {
                    __nv_bfloat16 hi, lo; bsplit(x[r], hi, lo);
                    sm.abhi[(r0+r)*AS2 + r0 + lane] = hi;
                    sm.ablo[(r0+r)*AS2 + r0 + lane] = lo;
                }
            }
        } else {
            int t = (warp - 4) * 32 + lane;
            int dv = t >> 2, i0 = (t & 3) * 4;
            unsigned hh, ll;
            bsplit2(sm.v[(i0+0)*VS + dv], sm.v[(i0+1)*VS + dv], hh, ll);
            *(unsigned*)&sm.rhi[dv*VTS + i0] = hh; *(unsigned*)&sm.rlo[dv*VTS + i0] = ll;
            bsplit2(sm.v[(i0+2)*VS + dv], sm.v[(i0+3)*VS + dv], hh, ll);
            *(unsigned*)&sm.rhi[dv*VTS + i0+2] = hh; *(unsigned*)&sm.rlo[dv*VTS + i0+2] = ll;
        }
        __syncthreads();

        // solve blocks via MMA
#pragma unroll
        for (int blk = 0; blk < 4; ++blk) {
            if (blk > 0) {
                if (warp < 4) {   // rhs_blk = v + A_off @ v_new_prev -> rhi/rlo
                    const int i0 = blk * 16, n0 = warp * 8;
                    float acc[4] = {0, 0, 0, 0};
                    unsigned aAh = sm_addr(&sm.abhi[(i0+lr)*AS2 + lc8]);
                    unsigned aAl = sm_addr(&sm.ablo[(i0+lr)*AS2 + lc8]);
                    unsigned bVh = sm_addr(&sm.vthi[(n0+lr2)*VTS + lc2]);
                    unsigned bVl = sm_addr(&sm.vtlo[(n0+lr2)*VTS + lc2]);
                    for (int ks = 0; ks < blk; ++ks) {
                        unsigned ah[4], al[4], bh2[2], bl2[2];
                        ldsm4(ah, aAh + ks*32); ldsm4(al, aAl + ks*32);
                        ldsm2(bh2, bVh + ks*32); ldsm2(bl2, bVl + ks*32);
                        mma_p3(acc, ah, al, bh2[0], bh2[1], bl2[0], bl2[1]);
                    }
#pragma unroll
                    for (int e = 0; e < 4; ++e) {
                        int i = i0 + gq_ + ((e >> 1) << 3);
                        int dv = n0 + 2 * tig + (e & 1);
                        float r = sm.v[i * VS + dv] + acc[e];
                        __nv_bfloat16 hi, lo; bsplit(r, hi, lo);
                        sm.rhi[dv * VTS + (i - i0)] = hi;
                        sm.rlo[dv * VTS + (i - i0)] = lo;
                    }
                }
                __syncthreads();
            }
            if (warp < 4) {       // v_new_blk = Ti @ rhs_blk
                const int i0 = blk * 16, n0 = warp * 8;
                unsigned ah[4], al[4], bh2[2], bl2[2];
                ldsm4(ah, sm_addr(&sm.abhi[(i0+lr)*AS2 + i0 + lc8]));
                ldsm4(al, sm_addr(&sm.ablo[(i0+lr)*AS2 + i0 + lc8]));
                ldsm2(bh2, sm_addr(&sm.rhi[(n0+lr2)*VTS + lc2]));
                ldsm2(bl2, sm_addr(&sm.rlo[(n0+lr2)*VTS + lc2]));
                float acc[4] = {0, 0, 0, 0};
                mma_p3(acc, ah, al, bh2[0], bh2[1], bl2[0], bl2[1]);
#pragma unroll
                for (int e = 0; e < 4; ++e) {
                    int i = i0 + gq_ + ((e >> 1) << 3);
                    int dv = n0 + 2 * tig + (e & 1);
                    sm.v[i * VS + dv] = acc[e];
                    __nv_bfloat16 hi, lo; bsplit(acc[e], hi, lo);
                    sm.vthi[dv * VTS + i] = hi;
                    sm.vtlo[dv * VTS + i] = lo;
                }
            }
            __syncthreads();
        }

        // vd = (v_new * kdec)^T -> rhi/rlo
        {
            int dv = tid >> 3, c0 = (tid & 7) * 8;
#pragma unroll
            for (int cc2 = 0; cc2 < 8; cc2 += 2) {
                int c = c0 + cc2;
                unsigned hh, ll;
                bsplit2(sm.v[c * VS + dv] * sm.kdec[c],
                        sm.v[(c + 1) * VS + dv] * sm.kdec[c + 1], hh, ll);
                *(unsigned*)&sm.rhi[dv*VTS + c] = hh;
                *(unsigned*)&sm.rlo[dv*VTS + c] = ll;
            }
        }
        __syncthreads();

        // P4: out^T = S^T@Qg^T + vnewT@attn^T
        {
            const int m0 = (warp & 1) * 16, n0 = (warp >> 1) * 16;
            float acc[2][4] = {};
            {
                unsigned aSh = sm_addr(&sm.shi[(m0+lr)*KHS + lc8]);
                unsigned aSl = sm_addr(&sm.slo[(m0+lr)*KHS + lc8]);
                unsigned bQh = sm_addr(&sm.qhi[(n0+lr)*KHS + lc8]);
                unsigned bQl = sm_addr(&sm.qlo[(n0+lr)*KHS + lc8]);
                for (int k0 = 0; k0 < DK; k0 += 16) {
                    unsigned ah[4], al[4], bh4[4], bl4[4];
                    ldsm4(ah, aSh + k0*2); ldsm4(al, aSl + k0*2);
                    ldsm4(bh4, bQh + k0*2); ldsm4(bl4, bQl + k0*2);
                    mma_p3(acc[0], ah, al, bh4[0], bh4[2], bl4[0], bl4[2]);
                    mma_p3(acc[1], ah, al, bh4[1], bh4[3], bl4[1], bl4[3]);
                }
            }
            {
                unsigned aVh = sm_addr(&sm.vthi[(m0+lr)*VTS + lc8]);
                unsigned aVl = sm_addr(&sm.vtlo[(m0+lr)*VTS + lc8]);
                unsigned bAh = sm_addr(&sm.athi[(n0+lr)*AS2 + lc8]);
                unsigned bAl = sm_addr(&sm.atlo[(n0+lr)*AS2 + lc8]);
                for (int k0 = 0; k0 < CC; k0 += 16) {
                    unsigned ah[4], al[4], bh4[4], bl4[4];
                    ldsm4(ah, aVh + k0*2); ldsm4(al, aVl + k0*2);
                    ldsm4(bh4, bAh + k0*2); ldsm4(bl4, bAl + k0*2);
                    mma_p3(acc[0], ah, al, bh4[0], bh4[2], bl4[0], bl4[2]);
                    mma_p3(acc[1], ah, al, bh4[1], bh4[3], bl4[1], bl4[3]);
                }
            }
#pragma unroll
            for (int nt = 0; nt < 2; ++nt)
#pragma unroll
                for (int e = 0; e < 4; ++e) {
                    int dv = m0 + gq_ + ((e >> 1) << 3);
                    int c = n0 + nt * 8 + 2 * tig + (e & 1);
                    size_t ob = (((size_t)b * S_LEN + s0 + c) * NH + h) * (size_t)DV +
                                split * DVS + dv;
                    gout[ob] = acc[nt][e];
                }
        }

        // P5: State^T = e^{glast} State^T + vd^T @ K
        {
            const int m0 = (warp & 1) * 16, n0 = (warp >> 1) * 32;
            float acc[4][4] = {};
            unsigned aVh = sm_addr(&sm.rhi[(m0+lr)*VTS + lc8]);
            unsigned aVl = sm_addr(&sm.rlo[(m0+lr)*VTS + lc8]);
            for (int k0 = 0; k0 < CC; k0 += 16) {
                unsigned ah[4], al[4];
                ldsm4(ah, aVh + k0*2); ldsm4(al, aVl + k0*2);
#pragma unroll
                for (int nt = 0; nt < 4; ++nt) {
                    int nn = n0 + nt * 8 + gq_;
                    unsigned bhh[2], bll[2];
                    ldBtrans(sm.khi, KHS, nn, k0, tig, bhh);
                    ldBtrans(sm.klo, KHS, nn, k0, tig, bll);
                    mma_p3(acc[nt], ah, al, bhh[0], bhh[1], bll[0], bll[1]);
                }
            }
            __syncthreads();   // P4 state reads done before RMW
            float egl = sm.egc[CC - 1];
#pragma unroll
            for (int nt = 0; nt < 4; ++nt)
#pragma unroll
                for (int e = 0; e < 4; ++e) {
                    int dv = m0 + gq_ + ((e >> 1) << 3);
                    int dk = n0 + nt * 8 + 2 * tig + (e & 1);
                    float s_old = __bfloat162float(sm.shi[dv * KHS + dk]) +
                                  __bfloat162float(sm.slo[dv * KHS + dk]);
                    float s = s_old * egl + acc[nt][e];
                    __nv_bfloat16 hi, lo; bsplit(s, hi, lo);
                    sm.shi[dv * KHS + dk] = hi;
                    sm.slo[dv * KHS + dk] = lo;
                }
        }
    }
}

extern "C" void kernel_launch(void* const* d_in, const int* in_sizes, int n_in,
                              void* d_out, int out_size) {
    const float* q = (const float*)d_in[0];
    const float* k = (const float*)d_in[1];
    const float* v = (const float*)d_in[2];
    const float* g = (const float*)d_in[3];
    const float* beta = (const float*)d_in[4];
    float* out = (float*)d_out;
    int B = in_sizes[0] / (S_LEN * NH * DK);
    if (B < 1) B = 1;
    cudaFuncSetAttribute(gdn_kernel, cudaFuncAttributeMaxDynamicSharedMemorySize,
                         (int)sizeof(SmemT));
    gdn_kernel<<<B * NH * SPLIT, NT, sizeof(SmemT)>>>(q, k, v, g, beta, out);
}

// round 9
// speedup vs baseline: 1.5293x; 1.5293x over previous
#include <cuda_runtime.h>
#include <cuda_bf16.h>
#include <math.h>

#define S_LEN 4096
#define NH 16
#define DK 128
#define DV 128
#define CC 64
#define NCHUNK 64
#define NT 256
#define SPLIT 4
#define DVS 32
#define NTILES 2048
#define KHS 136
#define AS2 72
#define VS 36
#define VTS 72

// packed bf16 pair scratch ([0]=hi,[1]=lo)
__device__ unsigned g_k[2][NTILES * 4096];   // [c][dk pair]
__device__ unsigned g_qg[2][NTILES * 4096];  // [c][dk pair]
__device__ unsigned g_ab[2][NTILES * 2048];  // [i][j pair]  (A strict-lower, Ti diag)
__device__ unsigned g_at[2][NTILES * 2048];  // [i][j pair]  (attn masked)
__device__ float g_sc[NTILES * 256];         // kw[64], kdec[64], beta[64], egl

__device__ __forceinline__ void bsplit(float x, __nv_bfloat16& hi, __nv_bfloat16& lo) {
    hi = __float2bfloat16(x);
    lo = __float2bfloat16(x - __bfloat162float(hi));
}
__device__ __forceinline__ void bsplit2(float x0, float x1, unsigned& h, unsigned& l) {
    __nv_bfloat16 h0 = __float2bfloat16(x0), h1 = __float2bfloat16(x1);
    __nv_bfloat16 g0 = __float2bfloat16(x0 - __bfloat162float(h0));
    __nv_bfloat16 g1 = __float2bfloat16(x1 - __bfloat162float(h1));
    h = (unsigned)*(unsigned short*)&h0 | ((unsigned)*(unsigned short*)&h1 << 16);
    l = (unsigned)*(unsigned short*)&g0 | ((unsigned)*(unsigned short*)&g1 << 16);
}
__device__ __forceinline__ unsigned sm_addr(const void* p) {
    return (unsigned)__cvta_generic_to_shared(p);
}
__device__ __forceinline__ void ldsm4(unsigned* r, unsigned a) {
    asm volatile("ldmatrix.sync.aligned.m8n8.x4.shared.b16 {%0,%1,%2,%3}, [%4];"
                 : "=r"(r[0]), "=r"(r[1]), "=r"(r[2]), "=r"(r[3]) : "r"(a));
}
__device__ __forceinline__ void ldsm2(unsigned* r, unsigned a) {
    asm volatile("ldmatrix.sync.aligned.m8n8.x2.shared.b16 {%0,%1}, [%2];"
                 : "=r"(r[0]), "=r"(r[1]) : "r"(a));
}
__device__ __forceinline__ void mma16816(float* d, unsigned a0, unsigned a1,
                                         unsigned a2, unsigned a3,
                                         unsigned b0, unsigned b1) {
    asm volatile("mma.sync.aligned.m16n8k16.row.col.f32.bf16.bf16.f32 "
                 "{%0,%1,%2,%3}, {%4,%5,%6,%7}, {%8,%9}, {%0,%1,%2,%3};\n"
                 : "+f"(d[0]), "+f"(d[1]), "+f"(d[2]), "+f"(d[3])
                 : "r"(a0), "r"(a1), "r"(a2), "r"(a3), "r"(b0), "r"(b1));
}
__device__ __forceinline__ void mma_p3(float* d, const unsigned* ah, const unsigned* al,
                                       unsigned bh0, unsigned bh1,
                                       unsigned bl0, unsigned bl1) {
    mma16816(d, ah[0], ah[1], ah[2], ah[3], bh0, bh1);
    mma16816(d, ah[0], ah[1], ah[2], ah[3], bl0, bl1);
    mma16816(d, al[0], al[1], al[2], al[3], bh0, bh1);
}
__device__ __forceinline__ void ldBtrans(const __nv_bfloat16* p, int stride, int n,
                                         int k0, int tig, unsigned* bb) {
    const unsigned short* s = reinterpret_cast<const unsigned short*>(p);
    int r = k0 + 2 * tig;
    unsigned l0 = s[r * stride + n], h0 = s[(r + 1) * stride + n];
    unsigned l1 = s[(r + 8) * stride + n], h1 = s[(r + 9) * stride + n];
    bb[0] = l0 | (h0 << 16);
    bb[1] = l1 | (h1 << 16);
}
__device__ __forceinline__ void cpa16(void* dst, const void* src) {
    unsigned d = (unsigned)__cvta_generic_to_shared(dst);
    asm volatile("cp.async.cg.shared.global [%0], [%1], 16;\n" :: "r"(d), "l"(src));
}

// ===================== kernel 1: prep (fully parallel) =====================
struct __align__(16) SmemP {
    float gst[CC], bst[CC], egc[CC], iegc[CC], kdec[CC], kw[CC], negbe[CC];
    __nv_bfloat16 khi[CC * KHS], klo[CC * KHS], qhi[CC * KHS], qlo[CC * KHS];
    __nv_bfloat16 abh[CC * AS2], abl[CC * AS2];
};

__global__ __launch_bounds__(NT, 2)
void gdn_prep(const float* __restrict__ gq, const float* __restrict__ gk,
              const float* __restrict__ gg, const float* __restrict__ gb) {
    extern __shared__ char smraw[];
    SmemP& sm = *reinterpret_cast<SmemP*>(smraw);
    const int tile = blockIdx.x, bh = tile / NCHUNK, n = tile % NCHUNK;
    const int b = bh / NH, h = bh % NH, s0 = n * CC;
    const int tid = threadIdx.x, warp = tid >> 5, lane = tid & 31;
    const int gq_ = lane >> 2, tig = lane & 3;
    const int lr = lane & 15, lc8 = (lane >> 4) << 3;
    const unsigned t4 = (unsigned)tile * 4096u, t2 = (unsigned)tile * 2048u;
    const float QSCALE = 0.08838834764831845f;

    if (tid < CC) {
        size_t gi = ((size_t)b * S_LEN + s0 + tid) * NH + h;
        sm.gst[tid] = gg[gi];
        sm.bst[tid] = gb[gi];
    }
    __syncthreads();
    if (warp == 0) {
        float a0 = sm.gst[lane], a1 = sm.gst[lane + 32];
#pragma unroll
        for (int o = 1; o < 32; o <<= 1) {
            float t = __shfl_up_sync(0xffffffffu, a0, o);
            if (lane >= o) a0 += t;
        }
        float tot0 = __shfl_sync(0xffffffffu, a0, 31);
#pragma unroll
        for (int o = 1; o < 32; o <<= 1) {
            float t = __shfl_up_sync(0xffffffffu, a1, o);
            if (lane >= o) a1 += t;
        }
        a1 += tot0;
        float glast = __shfl_sync(0xffffffffu, a1, 31);
        float e0 = expf(a0), e1 = expf(a1);
        sm.egc[lane] = e0;                sm.egc[lane + 32] = e1;
        sm.iegc[lane] = expf(-a0);        sm.iegc[lane + 32] = expf(-a1);
        sm.kdec[lane] = expf(glast - a0); sm.kdec[lane + 32] = expf(glast - a1);
        float b0 = sm.bst[lane], b1 = sm.bst[lane + 32];
        sm.kw[lane] = b0 * e0;            sm.kw[lane + 32] = b1 * e1;
        sm.negbe[lane] = -b0 * e0;        sm.negbe[lane + 32] = -b1 * e1;
    }
    __syncthreads();
    // scalar scratch out
    if (tid < CC) {
        size_t sb = (size_t)tile * 256;
        g_sc[sb + tid] = sm.kw[tid];
        g_sc[sb + 64 + tid] = sm.kdec[tid];
        g_sc[sb + 128 + tid] = sm.bst[tid];
        if (tid == 0) g_sc[sb + 192] = sm.egc[CC - 1];
    }
    // norm + split; k,qg also to scratch
#pragma unroll
    for (int it = 0; it < 4; ++it)
#pragma unroll
        for (int pp = 0; pp < 2; ++pp) {
            int rr = warp + it * 16 + pp * 8;
            size_t rb = (((size_t)b * S_LEN + s0 + rr) * NH + h) * (size_t)DK + lane * 4;
            float4 qv = *(const float4*)(gq + rb);
            float4 kv = *(const float4*)(gk + rb);
            float sq = qv.x*qv.x + qv.y*qv.y + qv.z*qv.z + qv.w*qv.w;
            float sk = kv.x*kv.x + kv.y*kv.y + kv.z*kv.z + kv.w*kv.w;
#pragma unroll
            for (int o = 16; o > 0; o >>= 1) {
                sq += __shfl_xor_sync(0xffffffffu, sq, o);
                sk += __shfl_xor_sync(0xffffffffu, sk, o);
            }
            float rqs = rsqrtf(sq + 1e-6f) * QSCALE * sm.egc[rr];
            float rks = rsqrtf(sk + 1e-6f);
            int c4 = lane * 4;
            unsigned hh, ll;
            bsplit2(kv.x * rks, kv.y * rks, hh, ll);
            *(unsigned*)&sm.khi[rr*KHS + c4] = hh; *(unsigned*)&sm.klo[rr*KHS + c4] = ll;
            g_k[0][t4 + rr*64 + lane*2] = hh; g_k[1][t4 + rr*64 + lane*2] = ll;
            bsplit2(kv.z * rks, kv.w * rks, hh, ll);
            *(unsigned*)&sm.khi[rr*KHS + c4+2] = hh; *(unsigned*)&sm.klo[rr*KHS + c4+2] = ll;
            g_k[0][t4 + rr*64 + lane*2 + 1] = hh; g_k[1][t4 + rr*64 + lane*2 + 1] = ll;
            bsplit2(qv.x * rqs, qv.y * rqs, hh, ll);
            *(unsigned*)&sm.qhi[rr*KHS + c4] = hh; *(unsigned*)&sm.qlo[rr*KHS + c4] = ll;
            g_qg[0][t4 + rr*64 + lane*2] = hh; g_qg[1][t4 + rr*64 + lane*2] = ll;
            bsplit2(qv.z * rqs, qv.w * rqs, hh, ll);
            *(unsigned*)&sm.qhi[rr*KHS + c4+2] = hh; *(unsigned*)&sm.qlo[rr*KHS + c4+2] = ll;
            g_qg[0][t4 + rr*64 + lane*2 + 1] = hh; g_qg[1][t4 + rr*64 + lane*2 + 1] = ll;
        }
    __syncthreads();

    // P1: G=K@K^T, QK=Qg@K^T (validated)
    {
        const int m0 = (warp >> 1) * 16, n0 = (warp & 1) * 32;
        float accG[4][4] = {}, accQ[4][4] = {};
        if (m0 + 15 >= n0) {
            unsigned aKh = sm_addr(&sm.khi[(m0+lr)*KHS + lc8]);
            unsigned aKl = sm_addr(&sm.klo[(m0+lr)*KHS + lc8]);
            unsigned aQh = sm_addr(&sm.qhi[(m0+lr)*KHS + lc8]);
            unsigned aQl = sm_addr(&sm.qlo[(m0+lr)*KHS + lc8]);
            unsigned b0a = sm_addr(&sm.khi[(n0+lr)*KHS + lc8]);
            unsigned b0b = sm_addr(&sm.klo[(n0+lr)*KHS + lc8]);
            unsigned b1a = sm_addr(&sm.khi[(n0+16+lr)*KHS + lc8]);
            unsigned b1b = sm_addr(&sm.klo[(n0+16+lr)*KHS + lc8]);
            const bool d1 = (m0+15 >= n0+8), d2 = (m0+15 >= n0+16), d3 = (m0+15 >= n0+24);
            for (int k0 = 0; k0 < DK; k0 += 16) {
                unsigned kh[4], kl[4], qh[4], ql[4], p0h[4], p0l[4];
                ldsm4(kh, aKh + k0*2); ldsm4(kl, aKl + k0*2);
                ldsm4(qh, aQh + k0*2); ldsm4(ql, aQl + k0*2);
                ldsm4(p0h, b0a + k0*2); ldsm4(p0l, b0b + k0*2);
                mma_p3(accG[0], kh, kl, p0h[0], p0h[2], p0l[0], p0l[2]);
                mma_p3(accQ[0], qh, ql, p0h[0], p0h[2], p0l[0], p0l[2]);
                if (d1) {
                    mma_p3(accG[1], kh, kl, p0h[1], p0h[3], p0l[1], p0l[3]);
                    mma_p3(accQ[1], qh, ql, p0h[1], p0h[3], p0l[1], p0l[3]);
                }
                if (d2) {
                    unsigned p1h[4], p1l[4];
                    ldsm4(p1h, b1a + k0*2); ldsm4(p1l, b1b + k0*2);
                    mma_p3(accG[2], kh, kl, p1h[0], p1h[2], p1l[0], p1l[2]);
                    mma_p3(accQ[2], qh, ql, p1h[0], p1h[2], p1l[0], p1l[2]);
                    if (d3) {
                        mma_p3(accG[3], kh, kl, p1h[1], p1h[3], p1l[1], p1l[3]);
                        mma_p3(accQ[3], qh, ql, p1h[1], p1h[3], p1l[1], p1l[3]);
                    }
                }
            }
        }
#pragma unroll
        for (int nt = 0; nt < 4; ++nt) {
            int j0 = n0 + nt * 8 + 2 * tig;
            float ie0 = sm.iegc[j0], ie1 = sm.iegc[j0 + 1];
#pragma unroll
            for (int rh = 0; rh < 2; ++rh) {
                int i = m0 + gq_ + rh * 8;
                float nb = sm.negbe[i];
                float av0 = (i > j0)      ? nb * ie0 * accG[nt][rh*2]   : 0.f;
                float av1 = (i > j0 + 1)  ? nb * ie1 * accG[nt][rh*2+1] : 0.f;
                float at0 = (i >= j0)     ? accQ[nt][rh*2]   * ie0 : 0.f;
                float at1 = (i >= j0 + 1) ? accQ[nt][rh*2+1] * ie1 : 0.f;
                unsigned hh, ll;
                bsplit2(av0, av1, hh, ll);
                *(unsigned*)&sm.abh[i*AS2 + j0] = hh;
                *(unsigned*)&sm.abl[i*AS2 + j0] = ll;
                bsplit2(at0, at1, hh, ll);
                g_at[0][t2 + i * 32 + (j0 >> 1)] = hh;
                g_at[1][t2 + i * 32 + (j0 >> 1)] = ll;
            }
        }
    }
    __syncthreads();
    // invert 16x16 diag blocks -> Ti in-place (validated)
    if (warp < 4 && lane < 16) {
        const int r0 = warp * 16;
        float x[16];
#pragma unroll
        for (int r = 0; r < 16; ++r) {
            float acc = (r == lane) ? 1.f : 0.f;
#pragma unroll
            for (int j = 0; j < 16; ++j)
                if (j < r) {
                    float a = __bfloat162float(sm.abh[(r0+r)*AS2 + r0+j]) +
                              __bfloat162float(sm.abl[(r0+r)*AS2 + r0+j]);
                    acc += a * x[j];
                }
            x[r] = acc;
        }
        __syncwarp(0x0000ffffu);
#pragma unroll
        for (int r = 0; r < 16; ++r) {
            __nv_bfloat16 hi, lo; bsplit(x[r], hi, lo);
            sm.abh[(r0+r)*AS2 + r0 + lane] = hi;
            sm.abl[(r0+r)*AS2 + r0 + lane] = lo;
        }
    }
    __syncthreads();
    for (int w = tid; w < 2048; w += NT) {
        int i = w >> 5, jp = w & 31;
        g_ab[0][t2 + w] = *(unsigned*)&sm.abh[i*AS2 + 2*jp];
        g_ab[1][t2 + w] = *(unsigned*)&sm.abl[i*AS2 + 2*jp];
    }
}

// ===================== kernel 2: scan (recurrent) =====================
struct __align__(16) SmemS {
    float v[CC * VS];
    float vraw[CC * 32];
    float scb[2][256];
    __nv_bfloat16 khi[2][CC * KHS], klo[2][CC * KHS];
    __nv_bfloat16 qhi[CC * KHS], qlo[CC * KHS];
    __nv_bfloat16 shi[32 * KHS], slo[32 * KHS];
    __nv_bfloat16 abh[CC * AS2], abl[CC * AS2];
    __nv_bfloat16 ath[CC * AS2], atl[CC * AS2];
    __nv_bfloat16 vth[32 * VTS], vtl[32 * VTS];
    __nv_bfloat16 rh[32 * VTS], rl[32 * VTS];
};

__global__ __launch_bounds__(NT, 1)
void gdn_scan(const float* __restrict__ gv, float* __restrict__ gout) {
    extern __shared__ char smraw[];
    SmemS& s = *reinterpret_cast<SmemS*>(smraw);
    const int bh = blockIdx.x / SPLIT, split = blockIdx.x % SPLIT;
    const int b = bh / NH, h = bh % NH;
    const int tid = threadIdx.x, warp = tid >> 5, lane = tid & 31;
    const int gq_ = lane >> 2, tig = lane & 3;
    const int lr = lane & 15, lc8 = (lane >> 4) << 3;
    const int lr2 = lane & 7, lc2 = ((lane >> 3) & 1) << 3;
    const int tile0 = bh * NCHUNK;

    const __nv_bfloat16 bz = __float2bfloat16(0.f);
    for (int i = tid; i < 32 * KHS; i += NT) { s.shi[i] = bz; s.slo[i] = bz; }

#define LD_KVS(nn, bf) do { \
    unsigned t4 = (unsigned)(tile0 + (nn)) * 4096u; \
    for (int i = tid; i < 1024; i += NT) { int r = i >> 4, j = i & 15; \
        cpa16(&s.khi[bf][r*KHS + j*8], &g_k[0][t4 + r*64 + j*4]); \
        cpa16(&s.klo[bf][r*KHS + j*8], &g_k[1][t4 + r*64 + j*4]); } \
    for (int i = tid; i < 512; i += NT) { int r = i >> 3, c = (i & 7) * 4; \
        cpa16(&s.vraw[r*32 + c], \
              gv + (((size_t)b * S_LEN + (nn) * CC + r) * NH + h) * (size_t)DV + \
              split * DVS + c); } \
    for (int i = tid; i < 64; i += NT) \
        cpa16(&s.scb[bf][i*4], &g_sc[(size_t)(tile0 + (nn)) * 256 + i*4]); \
    asm volatile("cp.async.commit_group;\n"); } while (0)
#define LD_AB(nn) do { \
    unsigned t2 = (unsigned)(tile0 + (nn)) * 2048u; \
    for (int i = tid; i < 512; i += NT) { int r = i >> 3, j = i & 7; \
        cpa16(&s.abh[r*AS2 + j*8], &g_ab[0][t2 + r*32 + j*4]); \
        cpa16(&s.abl[r*AS2 + j*8], &g_ab[1][t2 + r*32 + j*4]); } \
    asm volatile("cp.async.commit_group;\n"); } while (0)
#define LD_QA(nn) do { \
    unsigned t4 = (unsigned)(tile0 + (nn)) * 4096u; \
    unsigned t2 = (unsigned)(tile0 + (nn)) * 2048u; \
    for (int i = tid; i < 1024; i += NT) { int r = i >> 4, j = i & 15; \
        cpa16(&s.qhi[r*KHS + j*8], &g_qg[0][t4 + r*64 + j*4]); \
        cpa16(&s.qlo[r*KHS + j*8], &g_qg[1][t4 + r*64 + j*4]); } \
    for (int i = tid; i < 512; i += NT) { int r = i >> 3, j = i & 7; \
        cpa16(&s.ath[r*AS2 + j*8], &g_at[0][t2 + r*32 + j*4]); \
        cpa16(&s.atl[r*AS2 + j*8], &g_at[1][t2 + r*32 + j*4]); } \
    asm volatile("cp.async.commit_group;\n"); } while (0)

    LD_KVS(0, 0); LD_AB(0); LD_QA(0);

    for (int n = 0; n < NCHUNK; ++n) {
        const int cur = n & 1, s0 = n * CC;
        const int nn1 = (n + 1 < NCHUNK) ? n + 1 : n;   // clamp: uniform groups
        asm volatile("cp.async.wait_group 2;\n");       // KVS(n) ready
        __syncthreads();
        const float* sc = s.scb[cur];
        // v*beta -> rhs
        for (int i = tid; i < 512; i += NT) {
            int r = i >> 3, c = (i & 7) * 4;
            float4 t = *(const float4*)&s.vraw[r * 32 + c];
            float bt = sc[128 + r];
            t.x *= bt; t.y *= bt; t.z *= bt; t.w *= bt;
            *(float4*)&s.v[r * VS + c] = t;
        }
        __syncthreads();
        LD_KVS(nn1, cur ^ 1);

        // P2: rhs -= kw * (K @ State)
        {
            const int m0 = (warp & 1) * 16, n0 = (warp >> 1) * 16;
            float acc[2][4] = {};
            unsigned aSh = sm_addr(&s.shi[(m0+lr)*KHS + lc8]);
            unsigned aSl = sm_addr(&s.slo[(m0+lr)*KHS + lc8]);
            unsigned bKh = sm_addr(&s.khi[cur][(n0+lr)*KHS + lc8]);
            unsigned bKl = sm_addr(&s.klo[cur][(n0+lr)*KHS + lc8]);
            for (int k0 = 0; k0 < DK; k0 += 16) {
                unsigned ah[4], al[4], bh4[4], bl4[4];
                ldsm4(ah, aSh + k0*2); ldsm4(al, aSl + k0*2);
                ldsm4(bh4, bKh + k0*2); ldsm4(bl4, bKl + k0*2);
                mma_p3(acc[0], ah, al, bh4[0], bh4[2], bl4[0], bl4[2]);
                mma_p3(acc[1], ah, al, bh4[1], bh4[3], bl4[1], bl4[3]);
            }
#pragma unroll
            for (int nt = 0; nt < 2; ++nt)
#pragma unroll
                for (int e = 0; e < 4; ++e) {
                    int i = m0 + gq_ + ((e >> 1) << 3);
                    int j = n0 + nt * 8 + 2 * tig + (e & 1);
                    s.v[j * VS + i] -= sc[j] * acc[nt][e];
                }
        }
        __syncthreads();
        // split rhs block0 (warps 4-7)
        if (warp >= 4) {
            int t = (warp - 4) * 32 + lane;
            int dv = t >> 2, i0 = (t & 3) * 4;
            unsigned hh, ll;
            bsplit2(s.v[(i0+0)*VS + dv], s.v[(i0+1)*VS + dv], hh, ll);
            *(unsigned*)&s.rh[dv*VTS + i0] = hh; *(unsigned*)&s.rl[dv*VTS + i0] = ll;
            bsplit2(s.v[(i0+2)*VS + dv], s.v[(i0+3)*VS + dv], hh, ll);
            *(unsigned*)&s.rh[dv*VTS + i0+2] = hh; *(unsigned*)&s.rl[dv*VTS + i0+2] = ll;
        }
        asm volatile("cp.async.wait_group 2;\n");       // AB(n) ready
        __syncthreads();

        // solve blocks via MMA (validated)
#pragma unroll
        for (int blk = 0; blk < 4; ++blk) {
            if (blk > 0) {
                if (warp < 4) {
                    const int i0 = blk * 16, n0 = warp * 8;
                    float acc[4] = {0, 0, 0, 0};
                    unsigned aAh = sm_addr(&s.abh[(i0+lr)*AS2 + lc8]);
                    unsigned aAl = sm_addr(&s.abl[(i0+lr)*AS2 + lc8]);
                    unsigned bVh = sm_addr(&s.vth[(n0+lr2)*VTS + lc2]);
                    unsigned bVl = sm_addr(&s.vtl[(n0+lr2)*VTS + lc2]);
                    for (int ks = 0; ks < blk; ++ks) {
                        unsigned ah[4], al[4], bh2[2], bl2[2];
                        ldsm4(ah, aAh + ks*32); ldsm4(al, aAl + ks*32);
                        ldsm2(bh2, bVh + ks*32); ldsm2(bl2, bVl + ks*32);
                        mma_p3(acc, ah, al, bh2[0], bh2[1], bl2[0], bl2[1]);
                    }
#pragma unroll
                    for (int e = 0; e < 4; ++e) {
                        int i = i0 + gq_ + ((e >> 1) << 3);
                        int dv = n0 + 2 * tig + (e & 1);
                        float r = s.v[i * VS + dv] + acc[e];
                        __nv_bfloat16 hi, lo; bsplit(r, hi, lo);
                        s.rh[dv * VTS + (i - i0)] = hi;
                        s.rl[dv * VTS + (i - i0)] = lo;
                    }
                }
                __syncthreads();
            }
            if (warp < 4) {
                const int i0 = blk * 16, n0 = warp * 8;
                unsigned ah[4], al[4], bh2[2], bl2[2];
                ldsm4(ah, sm_addr(&s.abh[(i0+lr)*AS2 + i0 + lc8]));
                ldsm4(al, sm_addr(&s.abl[(i0+lr)*AS2 + i0 + lc8]));
                ldsm2(bh2, sm_addr(&s.rh[(n0+lr2)*VTS + lc2]));
                ldsm2(bl2, sm_addr(&s.rl[(n0+lr2)*VTS + lc2]));
                float acc[4] = {0, 0, 0, 0};
                mma_p3(acc, ah, al, bh2[0], bh2[1], bl2[0], bl2[1]);
#pragma unroll
                for (int e = 0; e < 4; ++e) {
                    int i = i0 + gq_ + ((e >> 1) << 3);
                    int dv = n0 + 2 * tig + (e & 1);
                    s.v[i * VS + dv] = acc[e];
                    __nv_bfloat16 hi, lo; bsplit(acc[e], hi, lo);
                    s.vth[dv * VTS + i] = hi;
                    s.vtl[dv * VTS + i] = lo;
                }
            }
            __syncthreads();
        }
        LD_AB(nn1);

        // vd = (v_new * kdec)^T -> rh/rl
        {
            int dv = tid >> 3, c0 = (tid & 7) * 8;
#pragma unroll
            for (int cc2 = 0; cc2 < 8; cc2 += 2) {
                int c = c0 + cc2;
                unsigned hh, ll;
                bsplit2(s.v[c * VS + dv] * sc[64 + c],
                        s.v[(c + 1) * VS + dv] * sc[64 + c + 1], hh, ll);
                *(unsigned*)&s.rh[dv*VTS + c] = hh;
                *(unsigned*)&s.rl[dv*VTS + c] = ll;
            }
        }
        asm volatile("cp.async.wait_group 2;\n");       // QA(n) ready
        __syncthreads();

        // P4: out^T = S^T@Qg^T + vn^T@attn^T
        {
            const int m0 = (warp & 1) * 16, n0 = (warp >> 1) * 16;
            float acc[2][4] = {};
            {
                unsigned aSh = sm_addr(&s.shi[(m0+lr)*KHS + lc8]);
                unsigned aSl = sm_addr(&s.slo[(m0+lr)*KHS + lc8]);
                unsigned bQh = sm_addr(&s.qhi[(n0+lr)*KHS + lc8]);
                unsigned bQl = sm_addr(&s.qlo[(n0+lr)*KHS + lc8]);
                for (int k0 = 0; k0 < DK; k0 += 16) {
                    unsigned ah[4], al[4], bh4[4], bl4[4];
                    ldsm4(ah, aSh + k0*2); ldsm4(al, aSl + k0*2);
                    ldsm4(bh4, bQh + k0*2); ldsm4(bl4, bQl + k0*2);
                    mma_p3(acc[0], ah, al, bh4[0], bh4[2], bl4[0], bl4[2]);
                    mma_p3(acc[1], ah, al, bh4[1], bh4[3], bl4[1], bl4[3]);
                }
            }
            {
                unsigned aVh = sm_addr(&s.vth[(m0+lr)*VTS + lc8]);
                unsigned aVl = sm_addr(&s.vtl[(m0+lr)*VTS + lc8]);
                unsigned bAh = sm_addr(&s.ath[(n0+lr)*AS2 + lc8]);
                unsigned bAl = sm_addr(&s.atl[(n0+lr)*AS2 + lc8]);
                for (int k0 = 0; k0 < CC; k0 += 16) {
                    unsigned ah[4], al[4], bh4[4], bl4[4];
                    ldsm4(ah, aVh + k0*2); ldsm4(al, aVl + k0*2);
                    ldsm4(bh4, bAh + k0*2); ldsm4(bl4, bAl + k0*2);
                    mma_p3(acc[0], ah, al, bh4[0], bh4[2], bl4[0], bl4[2]);
                    mma_p3(acc[1], ah, al, bh4[1], bh4[3], bl4[1], bl4[3]);
                }
            }
#pragma unroll
            for (int nt = 0; nt < 2; ++nt)
#pragma unroll
                for (int e = 0; e < 4; ++e) {
                    int dv = m0 + gq_ + ((e >> 1) << 3);
                    int c = n0 + nt * 8 + 2 * tig + (e & 1);
                    gout[(((size_t)b * S_LEN + s0 + c) * NH + h) * (size_t)DV +
                         split * DVS + dv] = acc[nt][e];
                }
        }
        __syncthreads();
        LD_QA(nn1);

        // P5: State^T = egl*State^T + vd^T @ K
        {
            const int m0 = (warp & 1) * 16, n0 = (warp >> 1) * 32;
            float acc[4][4] = {};
            unsigned aVh = sm_addr(&s.rh[(m0+lr)*VTS + lc8]);
            unsigned aVl = sm_addr(&s.rl[(m0+lr)*VTS + lc8]);
            const __nv_bfloat16* kb_h = s.khi[cur];
            const __nv_bfloat16* kb_l = s.klo[cur];
            for (int k0 = 0; k0 < CC; k0 += 16) {
                unsigned ah[4], al[4];
                ldsm4(ah, aVh + k0*2); ldsm4(al, aVl + k0*2);
#pragma unroll
                for (int nt = 0; nt < 4; ++nt) {
                    int nn = n0 + nt * 8 + gq_;
                    unsigned bhh[2], bll[2];
                    ldBtrans(kb_h, KHS, nn, k0, tig, bhh);
                    ldBtrans(kb_l, KHS, nn, k0, tig, bll);
                    mma_p3(acc[nt], ah, al, bhh[0], bhh[1], bll[0], bll[1]);
                }
            }
            __syncthreads();
            float egl = sc[192];
#pragma unroll
            for (int nt = 0; nt < 4; ++nt)
#pragma unroll
                for (int e = 0; e < 4; ++e) {
                    int dv = m0 + gq_ + ((e >> 1) << 3);
                    int dk = n0 + nt * 8 + 2 * tig + (e & 1);
                    float s_old = __bfloat162float(s.shi[dv * KHS + dk]) +
                                  __bfloat162float(s.slo[dv * KHS + dk]);
                    float sv = s_old * egl + acc[nt][e];
                    __nv_bfloat16 hi, lo; bsplit(sv, hi, lo);
                    s.shi[dv * KHS + dk] = hi;
                    s.slo[dv * KHS + dk] = lo;
                }
        }
    }
}

extern "C" void kernel_launch(void* const* d_in, const int* in_sizes, int n_in,
                              void* d_out, int out_size) {
    const float* q = (const float*)d_in[0];
    const float* k = (const float*)d_in[1];
    const float* v = (const float*)d_in[2];
    const float* g = (const float*)d_in[3];
    const float* beta = (const float*)d_in[4];
    float* out = (float*)d_out;
    int B = in_sizes[0] / (S_LEN * NH * DK);
    if (B < 1) B = 1;
    cudaFuncSetAttribute(gdn_prep, cudaFuncAttributeMaxDynamicSharedMemorySize,
                         (int)sizeof(SmemP));
    cudaFuncSetAttribute(gdn_scan, cudaFuncAttributeMaxDynamicSharedMemorySize,
                         (int)sizeof(SmemS));
    gdn_prep<<<B * NH * NCHUNK, NT, sizeof(SmemP)>>>(q, k, g, beta);
    gdn_scan<<<B * NH * SPLIT, NT, sizeof(SmemS)>>>(v, out);
}